// round 13
// baseline (speedup 1.0000x reference)
#include <cuda_runtime.h>

// ---------------------------------------------------------------------------
// signalEncoding: B=256, S=512, SF=4, NSIG=50
// prep+wcomp merged (one launch). sig: 256 thr, 2 pos/thread, swizzled SMEM,
// ull f32x2, 4 CTAs/SM (32 warps). L12 composed (4->4 k11) + SELU;
// L34 composed (4->1 k13) from H2; no H3. Edge outputs distributed:
// L12 edges on tids 0..15 (warp 0), L34 edges on tids 32..39 (warp 1).
// ---------------------------------------------------------------------------

#define NPOS 512
#define HALO 8
#define CST  528
#define NBP  128
#define NSIG 50
#define NITEM (NBP * NSIG)   // 6400
#define NCTA  592            // 4 CTAs/SM * 148 SMs = one wave
#define WSTRIDE 948
#define WTOTAL  948
#define WCOPY   358          // ull copied to smem (floats 0..715)

typedef unsigned long long ull;

// ull-index offsets into weight block (splatted f32x2 sections)
#define F2_W12S  0    // [o*48 + c*12 + t] t<11 real (192)
#define F2_BE12S 192  // [o] (4)
#define F2_W34S  196  // [c*13 + t] (52)
#define F2_BE34S 248  // (1)
// raw float offsets
#define OFF_W3R  498  // 40: [m*20 + c*5 + k]
#define OFF_B3R  538  // 2
#define OFF_W4R  540  // 10: [m*5 + j]
#define OFF_B4R  550  // 1
#define OFF_W2R  551  // 160
#define OFF_B2R  711  // 4
#define OFF_W1R  716  // 224 (global only)
#define OFF_B1R  940  // 8   (global only)

__device__ __forceinline__ int sidx(int c, int p) {
    int q = p + HALO;
    return c * CST + (q ^ ((q >> 4) & 3));
}

__device__ __forceinline__ int refl(int q) {
    q = q < 0 ? -q : q;
    return q > 511 ? 1022 - q : q;
}

// ---- ull-pure packed math ----
__device__ __forceinline__ ull ffma2u(ull a, ull b, ull c) {
    ull d;
    asm("fma.rn.f32x2 %0, %1, %2, %3;" : "=l"(d) : "l"(a), "l"(b), "l"(c));
    return d;
}
__device__ __forceinline__ float ulo(ull v) { return __uint_as_float((unsigned)v); }
__device__ __forceinline__ float uhi(ull v) { return __uint_as_float((unsigned)(v >> 32)); }
__device__ __forceinline__ ull upack(float x, float y) {
    return (ull)__float_as_uint(x) | ((ull)__float_as_uint(y) << 32);
}
__device__ __forceinline__ float selu_f(float x) {
    const float SC = 1.0507009873554805f;
    const float SA = 1.7580993408473766f;
    return x > 0.f ? SC * x : SA * (__expf(x) - 1.0f);
}
__device__ __forceinline__ ull selu_u(ull v) {
    return upack(selu_f(ulo(v)), selu_f(uhi(v)));
}

// ---- float2 helpers for prep ----
union F2U { float2 f; unsigned long long u; };
__device__ __forceinline__ float2 ffma2(float2 a, float2 b, float2 c) {
    F2U ua, ub, uc, ud;
    ua.f = a; ub.f = b; uc.f = c;
    asm("fma.rn.f32x2 %0, %1, %2, %3;" : "=l"(ud.u) : "l"(ua.u), "l"(ub.u), "l"(uc.u));
    return ud.f;
}
__device__ __forceinline__ float2 splat(float w) { return make_float2(w, w); }
__device__ __forceinline__ float2 add2(float2 a, float2 b) {
    return make_float2(a.x + b.x, a.y + b.y);
}
__device__ __forceinline__ float selu_s(float x) {
    const float SC = 1.0507009873554805f;
    const float SA = 1.7580993408473766f;
    return x > 0.f ? SC * x : SA * expm1f(x);
}
__device__ __forceinline__ float2 selu2(float2 v) {
    return make_float2(selu_s(v.x), selu_s(v.y));
}
__device__ __forceinline__ void fill_halo_sw(float2* buf, int C, int tid) {
    if (tid < C * 8) {
        int c = tid >> 3, k = tid & 7;
        if (k < 4) { int i = k + 1; buf[sidx(c, -i)]      = buf[sidx(c, i)]; }
        else       { int i = k - 3; buf[sidx(c, 511 + i)] = buf[sidx(c, 511 - i)]; }
    }
}

__device__ float2 g_D[NBP * 4 * NPOS];
__device__ __align__(16) float g_W[NSIG * WSTRIDE];

// ---------------------------------------------------------------------------
// wcomp body (device function, 128 threads per signal) — unchanged
// ---------------------------------------------------------------------------

__device__ void wcomp_body(int sig, int t,
                           const float* sw1, const float* sb1,
                           const float* sw2, const float* sb2,
                           const float* sw3, const float* sb3,
                           const float* sw4, const float* sb4) {
    float* w = g_W + sig * WSTRIDE;
    for (int i = t; i < WTOTAL; i += 128) {
        float v;
        if (i < 384) {
            int k = i >> 1, o = k / 48, r = k % 48, c = r / 12, tt = r % 12;
            if (tt == 11) v = 0.f;
            else {
                float s = 0.f;
                const float* w2p = sw2 + sig * 160 + o * 40;
                const float* w1p = sw1 + sig * 224;
                #pragma unroll
                for (int m = 0; m < 8; m++)
                    #pragma unroll
                    for (int j2 = 0; j2 < 5; j2++) {
                        int j1 = tt - j2;
                        if (j1 >= 0 && j1 <= 6)
                            s += w2p[m * 5 + j2] * w1p[m * 28 + c * 7 + j1];
                    }
                v = s;
            }
        } else if (i < 392) {
            int o = (i - 384) >> 1;
            float s = sb2[sig * 4 + o];
            #pragma unroll
            for (int m = 0; m < 8; m++) {
                float sm_ = 0.f;
                #pragma unroll
                for (int j2 = 0; j2 < 5; j2++) sm_ += sw2[sig * 160 + o * 40 + m * 5 + j2];
                s += sm_ * sb1[sig * 8 + m];
            }
            v = s;
        } else if (i < 496) {
            int k = (i - 392) >> 1, c = k / 13, tt = k % 13;
            float s = 0.f;
            #pragma unroll
            for (int m = 0; m < 2; m++)
                #pragma unroll
                for (int j4 = 0; j4 < 5; j4++) {
                    int j3 = tt - 2 * j4;
                    if (j3 >= 0 && j3 <= 4)
                        s += sw4[sig * 10 + m * 5 + j4] * sw3[sig * 40 + m * 20 + c * 5 + j3];
                }
            v = s;
        } else if (i < 498) {
            float s = sb4[sig];
            #pragma unroll
            for (int m = 0; m < 2; m++) {
                float sm_ = 0.f;
                #pragma unroll
                for (int j4 = 0; j4 < 5; j4++) sm_ += sw4[sig * 10 + m * 5 + j4];
                s += sm_ * sb3[sig * 2 + m];
            }
            v = s;
        } else if (i < 538) {
            v = sw3[sig * 40 + (i - OFF_W3R)];
        } else if (i < 540) {
            v = sb3[sig * 2 + (i - OFF_B3R)];
        } else if (i < 550) {
            v = sw4[sig * 10 + (i - OFF_W4R)];
        } else if (i < 551) {
            v = sb4[sig];
        } else if (i < 711) {
            v = sw2[sig * 160 + (i - OFF_W2R)];
        } else if (i < 715) {
            v = sb2[sig * 4 + (i - OFF_B2R)];
        } else if (i < 716) {
            v = 0.f;
        } else if (i < 940) {
            v = sw1[sig * 224 + (i - OFF_W1R)];
        } else {
            v = sb1[sig * 8 + (i - OFF_B1R)];
        }
        w[i] = v;
    }
}

// ---------------------------------------------------------------------------
// merged prep (+wcomp tail blocks). grid = 128 + 50, block = 512. (unchanged)
// ---------------------------------------------------------------------------

__device__ __forceinline__ void shared_conv1(const float2* S, float2* Dst,
                                             const float* w1, const float* b1, int t) {
    #pragma unroll
    for (int o = 0; o < 8; o++) {
        float2 acc = splat(b1[o]);
        #pragma unroll
        for (int c = 0; c < 4; c++)
            #pragma unroll
            for (int j = 0; j < 5; j++) {
                float w = w1[o * 20 + c * 5 + j];
                acc = ffma2(splat(w), S[sidx(c, t - 2 + j)], acc);
            }
        Dst[sidx(o, t)] = selu2(acc);
    }
}

__device__ __forceinline__ void shared_conv2(const float2* S, const float* w2,
                                             const float* b2, int t, float2 out[4]) {
    #pragma unroll
    for (int o = 0; o < 4; o++) {
        float2 acc = splat(b2[o]);
        #pragma unroll
        for (int c = 0; c < 8; c++)
            #pragma unroll
            for (int j = 0; j < 5; j++) {
                float w = w2[o * 40 + c * 5 + j];
                acc = ffma2(splat(w), S[sidx(c, t - 4 + 2 * j)], acc);
            }
        out[o] = acc;
    }
}

extern "C" __global__ void __launch_bounds__(512)
prep_kernel(const float* __restrict__ lat,
            const float* __restrict__ sw1, const float* __restrict__ sb1,
            const float* __restrict__ sw2, const float* __restrict__ sb2,
            const float* __restrict__ lng, const float* __restrict__ lnb,
            const float* __restrict__ gw1, const float* __restrict__ gb1,
            const float* __restrict__ gw2, const float* __restrict__ gb2,
            const float* __restrict__ gw3, const float* __restrict__ gb3,
            const float* __restrict__ gw4, const float* __restrict__ gb4) {
    if (blockIdx.x >= NBP) {
        if (threadIdx.x < 128)
            wcomp_body(blockIdx.x - NBP, threadIdx.x,
                       gw1, gb1, gw2, gb2, gw3, gb3, gw4, gb4);
        return;
    }

    extern __shared__ unsigned char sm[];
    float2* X   = (float2*)sm;
    float2* A   = X + 4 * CST;
    float2* Bu  = A + 8 * CST;
    float*  W   = (float*)(Bu + 4 * CST);
    float2* RED = (float2*)(W + 336);

    const int t  = threadIdx.x;
    const int bp = blockIdx.x;
    const int lane = t & 31, wid = t >> 5;

    if (t < 332) {
        float v;
        if      (t < 160) v = sw1[t];
        else if (t < 168) v = sb1[t - 160];
        else if (t < 328) v = sw2[t - 168];
        else              v = sb2[t - 328];
        W[t] = v;
    }
    const float* w1 = W, * b1 = W + 160, * w2 = W + 168, * b2 = W + 328;

    float4 v0 = reinterpret_cast<const float4*>(lat + (size_t)(2 * bp)     * 2048)[t];
    float4 v1 = reinterpret_cast<const float4*>(lat + (size_t)(2 * bp + 1) * 2048)[t];
    X[sidx(0, t)] = make_float2(v0.x, v1.x);
    X[sidx(1, t)] = make_float2(v0.y, v1.y);
    X[sidx(2, t)] = make_float2(v0.z, v1.z);
    X[sidx(3, t)] = make_float2(v0.w, v1.w);
    __syncthreads();
    fill_halo_sw(X, 4, t);
    __syncthreads();

    shared_conv1(X, A, w1, b1, t);
    __syncthreads(); fill_halo_sw(A, 8, t); __syncthreads();
    {
        float2 tmp[4];
        shared_conv2(A, w2, b2, t, tmp);
        __syncthreads();
        #pragma unroll
        for (int c = 0; c < 4; c++) Bu[sidx(c, t)] = tmp[c];
    }
    __syncthreads(); fill_halo_sw(Bu, 4, t); __syncthreads();

    shared_conv1(Bu, A, w1, b1, t);
    __syncthreads(); fill_halo_sw(A, 8, t); __syncthreads();
    float2 dv[4];
    {
        float2 cc[4];
        shared_conv2(A, w2, b2, t, cc);
        #pragma unroll
        for (int c = 0; c < 4; c++) dv[c] = add2(cc[c], X[sidx(c, t)]);
    }

    float2 mean[4], var[4];
    {
        float2 sv[4];
        #pragma unroll
        for (int c = 0; c < 4; c++) sv[c] = dv[c];
        #pragma unroll
        for (int c = 0; c < 4; c++)
            for (int off = 16; off; off >>= 1) {
                sv[c].x += __shfl_xor_sync(0xffffffffu, sv[c].x, off);
                sv[c].y += __shfl_xor_sync(0xffffffffu, sv[c].y, off);
            }
        if (lane == 0)
            #pragma unroll
            for (int c = 0; c < 4; c++) RED[c * 16 + wid] = sv[c];
        __syncthreads();
        if (t < 32) {
            #pragma unroll
            for (int c = 0; c < 4; c++) {
                float2 v = (lane < 16) ? RED[c * 16 + lane] : make_float2(0.f, 0.f);
                for (int off = 8; off; off >>= 1) {
                    v.x += __shfl_xor_sync(0xffffffffu, v.x, off);
                    v.y += __shfl_xor_sync(0xffffffffu, v.y, off);
                }
                if (lane == 0) RED[c * 16] = v;
            }
        }
        __syncthreads();
        const float inv = 1.0f / 512.0f;
        #pragma unroll
        for (int c = 0; c < 4; c++) {
            float2 s = RED[c * 16];
            mean[c] = make_float2(s.x * inv, s.y * inv);
        }
        __syncthreads();
    }
    {
        float2 sv[4];
        #pragma unroll
        for (int c = 0; c < 4; c++) {
            float dx = dv[c].x - mean[c].x, dy = dv[c].y - mean[c].y;
            sv[c] = make_float2(dx * dx, dy * dy);
        }
        #pragma unroll
        for (int c = 0; c < 4; c++)
            for (int off = 16; off; off >>= 1) {
                sv[c].x += __shfl_xor_sync(0xffffffffu, sv[c].x, off);
                sv[c].y += __shfl_xor_sync(0xffffffffu, sv[c].y, off);
            }
        if (lane == 0)
            #pragma unroll
            for (int c = 0; c < 4; c++) RED[c * 16 + wid] = sv[c];
        __syncthreads();
        if (t < 32) {
            #pragma unroll
            for (int c = 0; c < 4; c++) {
                float2 v = (lane < 16) ? RED[c * 16 + lane] : make_float2(0.f, 0.f);
                for (int off = 8; off; off >>= 1) {
                    v.x += __shfl_xor_sync(0xffffffffu, v.x, off);
                    v.y += __shfl_xor_sync(0xffffffffu, v.y, off);
                }
                if (lane == 0) RED[c * 16] = v;
            }
        }
        __syncthreads();
        const float inv = 1.0f / 512.0f;
        #pragma unroll
        for (int c = 0; c < 4; c++) {
            float2 s = RED[c * 16];
            var[c] = make_float2(s.x * inv, s.y * inv);
        }
    }

    const float EPS = 1e-10f;
    float g = lng[t], bb = lnb[t];
    #pragma unroll
    for (int c = 0; c < 4; c++) {
        float rx = 1.0f / sqrtf(var[c].x + EPS);
        float ry = 1.0f / sqrtf(var[c].y + EPS);
        float2 dn;
        dn.x = (dv[c].x - mean[c].x) * rx * g + bb;
        dn.y = (dv[c].y - mean[c].y) * ry * g + bb;
        g_D[(size_t)(bp * 4 + c) * NPOS + t] = dn;
    }
}

// ---------------------------------------------------------------------------
// sig: 256 threads, 2 pos/thread, 4 CTAs/SM (32 warps).
// ---------------------------------------------------------------------------

extern "C" __global__ void __launch_bounds__(256, 4)
sig_kernel(float* __restrict__ out) {
    extern __shared__ ull smu[];
    ull* Wsm = smu;                 // 360 ull
    ull* D   = smu + 360;           // 4*CST
    ull* H2  = D + 4 * CST;         // 4*CST
    ull* He  = H2 + 4 * CST;        // 64
    const float* Wf = (const float*)Wsm;

    const int tid  = threadIdx.x;
    const int base = tid * 2;
    const bool lo_edge = (tid == 0), hi_edge = (tid == 255);

    const int kcta  = blockIdx.x;
    const int start = (int)(((long long)kcta * NITEM) / NCTA);
    const int end   = (int)(((long long)(kcta + 1) * NITEM) / NCTA);

    int cur_bp = -1;

    for (int it = start; it < end; ++it) {
        const int bp  = it / NSIG;
        const int sig = it - bp * NSIG;

        __syncthreads();   // prior item's smem reads complete

        if (bp != cur_bp) {
            const ull* gd = (const ull*)(g_D + (size_t)bp * 4 * NPOS);
            for (int i = tid; i < 4 * NPOS; i += 256) {
                int c = i >> 9, pp = i & 511;
                ull v = gd[i];
                D[sidx(c, pp)] = v;
                if (pp >= 1 && pp <= 5)     D[sidx(c, -pp)]       = v;
                if (pp >= 506 && pp <= 510) D[sidx(c, 1022 - pp)] = v;
            }
            cur_bp = bp;
            __syncthreads();
        }

        const float* gw  = g_W + sig * WSTRIDE;
        const ull*   gwu = (const ull*)gw;

        // stage: tids >=64 copy weight block (192 thr); tids <64 compute H1 edges
        if (tid >= 64) {
            for (int i = tid - 64; i < WCOPY; i += 192) Wsm[i] = gwu[i];
        } else {
            int m = tid >> 3, kk = tid & 7;
            int q = kk < 4 ? kk : 508 + (kk - 4);
            float ax = gw[OFF_B1R + m], ay = ax;
            const float* w1p = gw + OFF_W1R + m * 28;
            #pragma unroll
            for (int c = 0; c < 4; c++)
                #pragma unroll
                for (int j1 = 0; j1 < 7; j1++) {
                    float w = w1p[c * 7 + j1];
                    ull dv = D[sidx(c, q - 3 + j1)];
                    ax = fmaf(w, ulo(dv), ax);
                    ay = fmaf(w, uhi(dv), ay);
                }
            He[tid] = upack(ax, ay);
        }
        __syncthreads();

        // ---- L12: composed 4->4 k11 (uniform, 2 pos); edge cells distributed ----
        {
            ull acc[4][2];
            #pragma unroll
            for (int o = 0; o < 4; o++) {
                ull b = Wsm[F2_BE12S + o];
                acc[o][0] = b; acc[o][1] = b;
            }
            #pragma unroll
            for (int c = 0; c < 4; c++) {
                ull din[12];
                #pragma unroll
                for (int t = 0; t < 12; t++) din[t] = D[sidx(c, base - 5 + t)];
                #pragma unroll
                for (int o = 0; o < 4; o++) {
                    const ulonglong2* wp2 =
                        (const ulonglong2*)(Wsm + F2_W12S + o * 48 + c * 12);
                    #pragma unroll
                    for (int tt = 0; tt < 5; tt++) {
                        ulonglong2 wq = wp2[tt];
                        acc[o][0] = ffma2u(wq.x, din[2 * tt],     acc[o][0]);
                        acc[o][1] = ffma2u(wq.x, din[2 * tt + 1], acc[o][1]);
                        acc[o][0] = ffma2u(wq.y, din[2 * tt + 1], acc[o][0]);
                        acc[o][1] = ffma2u(wq.y, din[2 * tt + 2], acc[o][1]);
                    }
                    ull w10 = Wsm[F2_W12S + o * 48 + c * 12 + 10];
                    acc[o][0] = ffma2u(w10, din[10], acc[o][0]);
                    acc[o][1] = ffma2u(w10, din[11], acc[o][1]);
                }
            }
            // store composed values; p in {0,1,510,511} written by edge tasks
            if (!lo_edge && !hi_edge) {
                #pragma unroll
                for (int o = 0; o < 4; o++)
                    #pragma unroll
                    for (int r = 0; r < 2; r++) {
                        int p = base + r;
                        ull v = selu_u(acc[o][r]);
                        H2[sidx(o, p)] = v;
                        if (p >= 2 && p <= 6)     H2[sidx(o, -p)]       = v;
                        if (p >= 505 && p <= 509) H2[sidx(o, 1022 - p)] = v;
                    }
            }
            // distributed L12 edge tasks: tid k<16 -> (e,o), p in {0,1,510,511}
            if (tid < 16) {
                int e = tid >> 2, o = tid & 3;
                int p = (e < 2) ? e : 508 + e;
                float ax = Wf[OFF_B2R + o], ay = ax;
                #pragma unroll
                for (int m = 0; m < 8; m++)
                    #pragma unroll
                    for (int j2 = 0; j2 < 5; j2++) {
                        int q = refl(p - 2 + j2);
                        int k = q < 8 ? q : q - 504;
                        float w = Wf[OFF_W2R + o * 40 + m * 5 + j2];
                        ull he = He[m * 8 + k];
                        ax = fmaf(w, ulo(he), ax);
                        ay = fmaf(w, uhi(he), ay);
                    }
                ull v = upack(selu_f(ax), selu_f(ay));
                H2[sidx(o, p)] = v;
                if (e == 1) H2[sidx(o, -1)]  = v;   // q=-1  <- p=1
                if (e == 2) H2[sidx(o, 512)] = v;   // q=512 <- p=510
            }
        }
        __syncthreads();

        // ---- L34: composed 4->1 k13 from H2 + SELU -> out ----
        const size_t ob0 = ((size_t)(2 * bp)     * 50 + sig) * NPOS;
        const size_t ob1 = ((size_t)(2 * bp + 1) * 50 + sig) * NPOS;
        {
            ull a4[2];
            ull b = Wsm[F2_BE34S];
            a4[0] = b; a4[1] = b;
            #pragma unroll
            for (int c = 0; c < 4; c++) {
                ull h[14];
                #pragma unroll
                for (int t = 0; t < 14; t++) h[t] = H2[sidx(c, base - 6 + t)];
                const ull* wp = Wsm + F2_W34S + c * 13;
                #pragma unroll
                for (int t = 0; t < 13; t++) {
                    ull w = wp[t];
                    a4[0] = ffma2u(w, h[t],     a4[0]);
                    a4[1] = ffma2u(w, h[t + 1], a4[1]);
                }
            }
            if (tid >= 2 && tid <= 253) {
                ull v0 = selu_u(a4[0]), v1 = selu_u(a4[1]);
                *reinterpret_cast<float2*>(out + ob0 + base) =
                    make_float2(ulo(v0), ulo(v1));
                *reinterpret_cast<float2*>(out + ob1 + base) =
                    make_float2(uhi(v0), uhi(v1));
            }
        }
        // distributed L34 edge outputs on warp 1: tids 32..39 -> p in {0..3,508..511}
        if (tid >= 32 && tid < 40) {
            int k = tid - 32;
            int p = (k < 4) ? k : 504 + k;
            float ax = Wf[OFF_B4R], ay = ax;
            #pragma unroll
            for (int m = 0; m < 2; m++)
                #pragma unroll
                for (int j = 0; j < 5; j++) {
                    int s = refl(p - 4 + 2 * j);
                    float hx = Wf[OFF_B3R + m], hy = hx;
                    #pragma unroll
                    for (int c = 0; c < 4; c++)
                        #pragma unroll
                        for (int kk = 0; kk < 5; kk++) {
                            float w = Wf[OFF_W3R + m * 20 + c * 5 + kk];
                            ull hv = H2[sidx(c, s - 2 + kk)];
                            hx = fmaf(w, ulo(hv), hx);
                            hy = fmaf(w, uhi(hv), hy);
                        }
                    float w4v = Wf[OFF_W4R + m * 5 + j];
                    ax = fmaf(w4v, hx, ax);
                    ay = fmaf(w4v, hy, ay);
                }
            out[ob0 + p] = selu_f(ax);
            out[ob1 + p] = selu_f(ay);
        }
    }
}

// ---------------------------------------------------------------------------
// launch
// ---------------------------------------------------------------------------

static const int SMEM_PREP = (16 * CST) * (int)sizeof(float2) + 336 * 4 + 64 * (int)sizeof(float2);
static const int SMEM_SIG  = (360 + 8 * CST + 64) * (int)sizeof(ull);

extern "C" void kernel_launch(void* const* d_in, const int* in_sizes, int n_in,
                              void* d_out, int out_size) {
    const float* lat  = (const float*)d_in[0];
    const float* shw1 = (const float*)d_in[1];
    const float* shb1 = (const float*)d_in[2];
    const float* shw2 = (const float*)d_in[3];
    const float* shb2 = (const float*)d_in[4];
    const float* lng  = (const float*)d_in[5];
    const float* lnb  = (const float*)d_in[6];
    const float* sgw1 = (const float*)d_in[7];
    const float* sgb1 = (const float*)d_in[8];
    const float* sgw2 = (const float*)d_in[9];
    const float* sgb2 = (const float*)d_in[10];
    const float* sgw3 = (const float*)d_in[11];
    const float* sgb3 = (const float*)d_in[12];
    const float* sgw4 = (const float*)d_in[13];
    const float* sgb4 = (const float*)d_in[14];
    float* out = (float*)d_out;

    cudaFuncSetAttribute(prep_kernel, cudaFuncAttributeMaxDynamicSharedMemorySize, SMEM_PREP);
    cudaFuncSetAttribute(sig_kernel,  cudaFuncAttributeMaxDynamicSharedMemorySize, SMEM_SIG);

    prep_kernel<<<NBP + NSIG, 512, SMEM_PREP>>>(lat, shw1, shb1, shw2, shb2, lng, lnb,
                                                sgw1, sgb1, sgw2, sgb2,
                                                sgw3, sgb3, sgw4, sgb4);
    sig_kernel<<<NCTA, 256, SMEM_SIG>>>(out);
}

// round 14
// speedup vs baseline: 1.2207x; 1.2207x over previous
#include <cuda_runtime.h>

// ---------------------------------------------------------------------------
// signalEncoding: B=256, S=512, SF=4, NSIG=50
// prep+wcomp merged (one launch). sig: 128 thr, 4 pos/thread, swizzled SMEM,
// ull f32x2, 6 CTAs/SM. L12 composed (4->4 k11) + SELU; L34 composed
// (4->1 k13) from H2; no H3; 3 barriers/item. Branchless SELU.
// L12 edge tasks on warp 0 (tids 0..15); L34 edge tasks on warp 1 (tids 32..39).
// ---------------------------------------------------------------------------

#define NPOS 512
#define HALO 8
#define CST  528
#define NBP  128
#define NSIG 50
#define NITEM (NBP * NSIG)   // 6400
#define NCTA  888            // 6 CTAs/SM * 148 SMs = one wave
#define WSTRIDE 948
#define WTOTAL  948
#define WCOPY   358          // ull copied to smem (floats 0..715)

typedef unsigned long long ull;

// ull-index offsets into weight block (splatted f32x2 sections)
#define F2_W12S  0    // [o*48 + c*12 + t] t<11 real (192)
#define F2_BE12S 192  // [o] (4)
#define F2_W34S  196  // [c*13 + t] (52)
#define F2_BE34S 248  // (1)
// raw float offsets
#define OFF_W3R  498  // 40: [m*20 + c*5 + k]
#define OFF_B3R  538  // 2
#define OFF_W4R  540  // 10: [m*5 + j]
#define OFF_B4R  550  // 1
#define OFF_W2R  551  // 160
#define OFF_B2R  711  // 4
#define OFF_W1R  716  // 224 (global only)
#define OFF_B1R  940  // 8   (global only)

__device__ __forceinline__ int sidx(int c, int p) {
    int q = p + HALO;
    return c * CST + (q ^ ((q >> 4) & 3));
}

__device__ __forceinline__ int refl(int q) {
    q = q < 0 ? -q : q;
    return q > 511 ? 1022 - q : q;
}

// ---- ull-pure packed math ----
__device__ __forceinline__ ull ffma2u(ull a, ull b, ull c) {
    ull d;
    asm("fma.rn.f32x2 %0, %1, %2, %3;" : "=l"(d) : "l"(a), "l"(b), "l"(c));
    return d;
}
__device__ __forceinline__ float ulo(ull v) { return __uint_as_float((unsigned)v); }
__device__ __forceinline__ float uhi(ull v) { return __uint_as_float((unsigned)(v >> 32)); }
__device__ __forceinline__ ull upack(float x, float y) {
    return (ull)__float_as_uint(x) | ((ull)__float_as_uint(y) << 32);
}
// branchless SELU: fmax(SC*x,0) + fmin(SA*(exp(x)-1),0); exact selection since
// sign(SA*(exp(x)-1)) == sign(x). Overflow-safe (inf -> fmin(...,0)=0 path only
// occurs when x>0 where the negative term is clamped to 0 anyway).
__device__ __forceinline__ float selu_f(float x) {
    const float SC = 1.0507009873554805f;
    const float SA = 1.7580993408473766f;
    float p = SC * x;
    float e = SA * (__expf(x) - 1.0f);
    return fmaxf(p, 0.0f) + fminf(e, 0.0f);
}
__device__ __forceinline__ ull selu_u(ull v) {
    return upack(selu_f(ulo(v)), selu_f(uhi(v)));
}

// ---- float2 helpers for prep ----
union F2U { float2 f; unsigned long long u; };
__device__ __forceinline__ float2 ffma2(float2 a, float2 b, float2 c) {
    F2U ua, ub, uc, ud;
    ua.f = a; ub.f = b; uc.f = c;
    asm("fma.rn.f32x2 %0, %1, %2, %3;" : "=l"(ud.u) : "l"(ua.u), "l"(ub.u), "l"(uc.u));
    return ud.f;
}
__device__ __forceinline__ float2 splat(float w) { return make_float2(w, w); }
__device__ __forceinline__ float2 add2(float2 a, float2 b) {
    return make_float2(a.x + b.x, a.y + b.y);
}
__device__ __forceinline__ float selu_s(float x) {
    const float SC = 1.0507009873554805f;
    const float SA = 1.7580993408473766f;
    return x > 0.f ? SC * x : SA * expm1f(x);
}
__device__ __forceinline__ float2 selu2(float2 v) {
    return make_float2(selu_s(v.x), selu_s(v.y));
}
__device__ __forceinline__ void fill_halo_sw(float2* buf, int C, int tid) {
    if (tid < C * 8) {
        int c = tid >> 3, k = tid & 7;
        if (k < 4) { int i = k + 1; buf[sidx(c, -i)]      = buf[sidx(c, i)]; }
        else       { int i = k - 3; buf[sidx(c, 511 + i)] = buf[sidx(c, 511 - i)]; }
    }
}

__device__ float2 g_D[NBP * 4 * NPOS];
__device__ __align__(16) float g_W[NSIG * WSTRIDE];

// ---------------------------------------------------------------------------
// wcomp body (device function, 128 threads per signal)
// ---------------------------------------------------------------------------

__device__ void wcomp_body(int sig, int t,
                           const float* sw1, const float* sb1,
                           const float* sw2, const float* sb2,
                           const float* sw3, const float* sb3,
                           const float* sw4, const float* sb4) {
    float* w = g_W + sig * WSTRIDE;
    for (int i = t; i < WTOTAL; i += 128) {
        float v;
        if (i < 384) {
            int k = i >> 1, o = k / 48, r = k % 48, c = r / 12, tt = r % 12;
            if (tt == 11) v = 0.f;
            else {
                float s = 0.f;
                const float* w2p = sw2 + sig * 160 + o * 40;
                const float* w1p = sw1 + sig * 224;
                #pragma unroll
                for (int m = 0; m < 8; m++)
                    #pragma unroll
                    for (int j2 = 0; j2 < 5; j2++) {
                        int j1 = tt - j2;
                        if (j1 >= 0 && j1 <= 6)
                            s += w2p[m * 5 + j2] * w1p[m * 28 + c * 7 + j1];
                    }
                v = s;
            }
        } else if (i < 392) {
            int o = (i - 384) >> 1;
            float s = sb2[sig * 4 + o];
            #pragma unroll
            for (int m = 0; m < 8; m++) {
                float sm_ = 0.f;
                #pragma unroll
                for (int j2 = 0; j2 < 5; j2++) sm_ += sw2[sig * 160 + o * 40 + m * 5 + j2];
                s += sm_ * sb1[sig * 8 + m];
            }
            v = s;
        } else if (i < 496) {
            int k = (i - 392) >> 1, c = k / 13, tt = k % 13;
            float s = 0.f;
            #pragma unroll
            for (int m = 0; m < 2; m++)
                #pragma unroll
                for (int j4 = 0; j4 < 5; j4++) {
                    int j3 = tt - 2 * j4;
                    if (j3 >= 0 && j3 <= 4)
                        s += sw4[sig * 10 + m * 5 + j4] * sw3[sig * 40 + m * 20 + c * 5 + j3];
                }
            v = s;
        } else if (i < 498) {
            float s = sb4[sig];
            #pragma unroll
            for (int m = 0; m < 2; m++) {
                float sm_ = 0.f;
                #pragma unroll
                for (int j4 = 0; j4 < 5; j4++) sm_ += sw4[sig * 10 + m * 5 + j4];
                s += sm_ * sb3[sig * 2 + m];
            }
            v = s;
        } else if (i < 538) {
            v = sw3[sig * 40 + (i - OFF_W3R)];
        } else if (i < 540) {
            v = sb3[sig * 2 + (i - OFF_B3R)];
        } else if (i < 550) {
            v = sw4[sig * 10 + (i - OFF_W4R)];
        } else if (i < 551) {
            v = sb4[sig];
        } else if (i < 711) {
            v = sw2[sig * 160 + (i - OFF_W2R)];
        } else if (i < 715) {
            v = sb2[sig * 4 + (i - OFF_B2R)];
        } else if (i < 716) {
            v = 0.f;  // pad
        } else if (i < 940) {
            v = sw1[sig * 224 + (i - OFF_W1R)];
        } else {
            v = sb1[sig * 8 + (i - OFF_B1R)];
        }
        w[i] = v;
    }
}

// ---------------------------------------------------------------------------
// merged prep (+wcomp tail blocks). grid = 128 + 50, block = 512.
// ---------------------------------------------------------------------------

__device__ __forceinline__ void shared_conv1(const float2* S, float2* Dst,
                                             const float* w1, const float* b1, int t) {
    #pragma unroll
    for (int o = 0; o < 8; o++) {
        float2 acc = splat(b1[o]);
        #pragma unroll
        for (int c = 0; c < 4; c++)
            #pragma unroll
            for (int j = 0; j < 5; j++) {
                float w = w1[o * 20 + c * 5 + j];
                acc = ffma2(splat(w), S[sidx(c, t - 2 + j)], acc);
            }
        Dst[sidx(o, t)] = selu2(acc);
    }
}

__device__ __forceinline__ void shared_conv2(const float2* S, const float* w2,
                                             const float* b2, int t, float2 out[4]) {
    #pragma unroll
    for (int o = 0; o < 4; o++) {
        float2 acc = splat(b2[o]);
        #pragma unroll
        for (int c = 0; c < 8; c++)
            #pragma unroll
            for (int j = 0; j < 5; j++) {
                float w = w2[o * 40 + c * 5 + j];
                acc = ffma2(splat(w), S[sidx(c, t - 4 + 2 * j)], acc);
            }
        out[o] = acc;
    }
}

extern "C" __global__ void __launch_bounds__(512)
prep_kernel(const float* __restrict__ lat,
            const float* __restrict__ sw1, const float* __restrict__ sb1,
            const float* __restrict__ sw2, const float* __restrict__ sb2,
            const float* __restrict__ lng, const float* __restrict__ lnb,
            const float* __restrict__ gw1, const float* __restrict__ gb1,
            const float* __restrict__ gw2, const float* __restrict__ gb2,
            const float* __restrict__ gw3, const float* __restrict__ gb3,
            const float* __restrict__ gw4, const float* __restrict__ gb4) {
    if (blockIdx.x >= NBP) {
        if (threadIdx.x < 128)
            wcomp_body(blockIdx.x - NBP, threadIdx.x,
                       gw1, gb1, gw2, gb2, gw3, gb3, gw4, gb4);
        return;
    }

    extern __shared__ unsigned char sm[];
    float2* X   = (float2*)sm;
    float2* A   = X + 4 * CST;
    float2* Bu  = A + 8 * CST;
    float*  W   = (float*)(Bu + 4 * CST);
    float2* RED = (float2*)(W + 336);

    const int t  = threadIdx.x;
    const int bp = blockIdx.x;
    const int lane = t & 31, wid = t >> 5;

    if (t < 332) {
        float v;
        if      (t < 160) v = sw1[t];
        else if (t < 168) v = sb1[t - 160];
        else if (t < 328) v = sw2[t - 168];
        else              v = sb2[t - 328];
        W[t] = v;
    }
    const float* w1 = W, * b1 = W + 160, * w2 = W + 168, * b2 = W + 328;

    float4 v0 = reinterpret_cast<const float4*>(lat + (size_t)(2 * bp)     * 2048)[t];
    float4 v1 = reinterpret_cast<const float4*>(lat + (size_t)(2 * bp + 1) * 2048)[t];
    X[sidx(0, t)] = make_float2(v0.x, v1.x);
    X[sidx(1, t)] = make_float2(v0.y, v1.y);
    X[sidx(2, t)] = make_float2(v0.z, v1.z);
    X[sidx(3, t)] = make_float2(v0.w, v1.w);
    __syncthreads();
    fill_halo_sw(X, 4, t);
    __syncthreads();

    shared_conv1(X, A, w1, b1, t);
    __syncthreads(); fill_halo_sw(A, 8, t); __syncthreads();
    {
        float2 tmp[4];
        shared_conv2(A, w2, b2, t, tmp);
        __syncthreads();
        #pragma unroll
        for (int c = 0; c < 4; c++) Bu[sidx(c, t)] = tmp[c];
    }
    __syncthreads(); fill_halo_sw(Bu, 4, t); __syncthreads();

    shared_conv1(Bu, A, w1, b1, t);
    __syncthreads(); fill_halo_sw(A, 8, t); __syncthreads();
    float2 dv[4];
    {
        float2 cc[4];
        shared_conv2(A, w2, b2, t, cc);
        #pragma unroll
        for (int c = 0; c < 4; c++) dv[c] = add2(cc[c], X[sidx(c, t)]);
    }

    float2 mean[4], var[4];
    {
        float2 sv[4];
        #pragma unroll
        for (int c = 0; c < 4; c++) sv[c] = dv[c];
        #pragma unroll
        for (int c = 0; c < 4; c++)
            for (int off = 16; off; off >>= 1) {
                sv[c].x += __shfl_xor_sync(0xffffffffu, sv[c].x, off);
                sv[c].y += __shfl_xor_sync(0xffffffffu, sv[c].y, off);
            }
        if (lane == 0)
            #pragma unroll
            for (int c = 0; c < 4; c++) RED[c * 16 + wid] = sv[c];
        __syncthreads();
        if (t < 32) {
            #pragma unroll
            for (int c = 0; c < 4; c++) {
                float2 v = (lane < 16) ? RED[c * 16 + lane] : make_float2(0.f, 0.f);
                for (int off = 8; off; off >>= 1) {
                    v.x += __shfl_xor_sync(0xffffffffu, v.x, off);
                    v.y += __shfl_xor_sync(0xffffffffu, v.y, off);
                }
                if (lane == 0) RED[c * 16] = v;
            }
        }
        __syncthreads();
        const float inv = 1.0f / 512.0f;
        #pragma unroll
        for (int c = 0; c < 4; c++) {
            float2 s = RED[c * 16];
            mean[c] = make_float2(s.x * inv, s.y * inv);
        }
        __syncthreads();
    }
    {
        float2 sv[4];
        #pragma unroll
        for (int c = 0; c < 4; c++) {
            float dx = dv[c].x - mean[c].x, dy = dv[c].y - mean[c].y;
            sv[c] = make_float2(dx * dx, dy * dy);
        }
        #pragma unroll
        for (int c = 0; c < 4; c++)
            for (int off = 16; off; off >>= 1) {
                sv[c].x += __shfl_xor_sync(0xffffffffu, sv[c].x, off);
                sv[c].y += __shfl_xor_sync(0xffffffffu, sv[c].y, off);
            }
        if (lane == 0)
            #pragma unroll
            for (int c = 0; c < 4; c++) RED[c * 16 + wid] = sv[c];
        __syncthreads();
        if (t < 32) {
            #pragma unroll
            for (int c = 0; c < 4; c++) {
                float2 v = (lane < 16) ? RED[c * 16 + lane] : make_float2(0.f, 0.f);
                for (int off = 8; off; off >>= 1) {
                    v.x += __shfl_xor_sync(0xffffffffu, v.x, off);
                    v.y += __shfl_xor_sync(0xffffffffu, v.y, off);
                }
                if (lane == 0) RED[c * 16] = v;
            }
        }
        __syncthreads();
        const float inv = 1.0f / 512.0f;
        #pragma unroll
        for (int c = 0; c < 4; c++) {
            float2 s = RED[c * 16];
            var[c] = make_float2(s.x * inv, s.y * inv);
        }
    }

    const float EPS = 1e-10f;
    float g = lng[t], bb = lnb[t];
    #pragma unroll
    for (int c = 0; c < 4; c++) {
        float rx = 1.0f / sqrtf(var[c].x + EPS);
        float ry = 1.0f / sqrtf(var[c].y + EPS);
        float2 dn;
        dn.x = (dv[c].x - mean[c].x) * rx * g + bb;
        dn.y = (dv[c].y - mean[c].y) * ry * g + bb;
        g_D[(size_t)(bp * 4 + c) * NPOS + t] = dn;
    }
}

// ---------------------------------------------------------------------------
// sig: 128 threads, 4 pos/thread, 6 CTAs/SM, no H3 (L34 composed).
// ---------------------------------------------------------------------------

extern "C" __global__ void __launch_bounds__(128, 6)
sig_kernel(float* __restrict__ out) {
    extern __shared__ ull smu[];
    ull* Wsm = smu;                 // 360 ull (WCOPY=358 + pad)
    ull* D   = smu + 360;           // 4*CST
    ull* H2  = D + 4 * CST;         // 4*CST
    ull* He  = H2 + 4 * CST;        // 64
    const float* Wf = (const float*)Wsm;

    const int tid  = threadIdx.x;
    const int base = tid * 4;
    const bool is_lo = (tid == 0), is_hi = (tid == 127);

    const int kcta  = blockIdx.x;
    const int start = (int)(((long long)kcta * NITEM) / NCTA);
    const int end   = (int)(((long long)(kcta + 1) * NITEM) / NCTA);

    int cur_bp = -1;

    for (int it = start; it < end; ++it) {
        const int bp  = it / NSIG;
        const int sig = it - bp * NSIG;

        __syncthreads();   // prior item's smem reads complete

        if (bp != cur_bp) {
            const ull* gd = (const ull*)(g_D + (size_t)bp * 4 * NPOS);
            for (int i = tid; i < 4 * NPOS; i += 128) {
                int c = i >> 9, pp = i & 511;
                ull v = gd[i];
                D[sidx(c, pp)] = v;
                if (pp >= 1 && pp <= 5)     D[sidx(c, -pp)]       = v;
                if (pp >= 506 && pp <= 510) D[sidx(c, 1022 - pp)] = v;
            }
            cur_bp = bp;
            __syncthreads();
        }

        const float* gw  = g_W + sig * WSTRIDE;
        const ull*   gwu = (const ull*)gw;

        // stage: tids >=64 copy weight block (vectorized); tids <64 compute H1 edges
        if (tid >= 64) {
            const ulonglong2* gwu2 = (const ulonglong2*)gwu;
            ulonglong2* Wsm2 = (ulonglong2*)Wsm;
            for (int i = tid - 64; i < WCOPY / 2; i += 64) Wsm2[i] = gwu2[i];
        } else {
            int m = tid >> 3, kk = tid & 7;
            int q = kk < 4 ? kk : 508 + (kk - 4);
            float ax = gw[OFF_B1R + m], ay = ax;
            const float* w1p = gw + OFF_W1R + m * 28;
            #pragma unroll
            for (int c = 0; c < 4; c++)
                #pragma unroll
                for (int j1 = 0; j1 < 7; j1++) {
                    float w = w1p[c * 7 + j1];
                    ull dv = D[sidx(c, q - 3 + j1)];
                    ax = fmaf(w, ulo(dv), ax);
                    ay = fmaf(w, uhi(dv), ay);
                }
            He[tid] = upack(ax, ay);
        }
        __syncthreads();

        // ---- L12: composed 4->4 k11 (uniform); edge cells distributed ----
        {
            ull acc[4][4];
            #pragma unroll
            for (int o = 0; o < 4; o++) {
                ull b = Wsm[F2_BE12S + o];
                #pragma unroll
                for (int r = 0; r < 4; r++) acc[o][r] = b;
            }
            #pragma unroll
            for (int c = 0; c < 4; c++) {
                ull din[14];
                #pragma unroll
                for (int t = 0; t < 14; t++) din[t] = D[sidx(c, base - 5 + t)];
                #pragma unroll
                for (int o = 0; o < 4; o++) {
                    const ulonglong2* wp2 =
                        (const ulonglong2*)(Wsm + F2_W12S + o * 48 + c * 12);
                    #pragma unroll
                    for (int tt = 0; tt < 5; tt++) {
                        ulonglong2 wq = wp2[tt];
                        #pragma unroll
                        for (int r = 0; r < 4; r++)
                            acc[o][r] = ffma2u(wq.x, din[2 * tt + r], acc[o][r]);
                        #pragma unroll
                        for (int r = 0; r < 4; r++)
                            acc[o][r] = ffma2u(wq.y, din[2 * tt + 1 + r], acc[o][r]);
                    }
                    ull w10 = Wsm[F2_W12S + o * 48 + c * 12 + 10];
                    #pragma unroll
                    for (int r = 0; r < 4; r++)
                        acc[o][r] = ffma2u(w10, din[10 + r], acc[o][r]);
                }
            }
            // store composed values; skip edge cells (p in {0,1,510,511});
            // owner-exact halo mirrors for q in [-6,-2] and [513,517]
            #pragma unroll
            for (int o = 0; o < 4; o++)
                #pragma unroll
                for (int r = 0; r < 4; r++) {
                    if ((is_lo && r < 2) || (is_hi && r >= 2)) continue;
                    ull v = selu_u(acc[o][r]);
                    H2[sidx(o, base + r)] = v;
                    if (is_lo) {
                        if (r == 2) H2[sidx(o, -2)] = v;
                        if (r == 3) H2[sidx(o, -3)] = v;
                    } else if (tid == 1) {
                        if (r == 0) H2[sidx(o, -4)] = v;
                        if (r == 1) H2[sidx(o, -5)] = v;
                        if (r == 2) H2[sidx(o, -6)] = v;
                    } else if (tid == 126) {
                        if (r == 1) H2[sidx(o, 517)] = v;
                        if (r == 2) H2[sidx(o, 516)] = v;
                        if (r == 3) H2[sidx(o, 515)] = v;
                    } else if (is_hi) {
                        if (r == 0) H2[sidx(o, 514)] = v;
                        if (r == 1) H2[sidx(o, 513)] = v;
                    }
                }
            // distributed L12 edge tasks: tid k<16 -> (e,o), p in {0,1,510,511}
            if (tid < 16) {
                int e = tid >> 2, o = tid & 3;
                int p = (e < 2) ? e : 508 + e;
                float ax = Wf[OFF_B2R + o], ay = ax;
                #pragma unroll
                for (int m = 0; m < 8; m++)
                    #pragma unroll
                    for (int j2 = 0; j2 < 5; j2++) {
                        int q = refl(p - 2 + j2);
                        int k = q < 8 ? q : q - 504;
                        float w = Wf[OFF_W2R + o * 40 + m * 5 + j2];
                        ull he = He[m * 8 + k];
                        ax = fmaf(w, ulo(he), ax);
                        ay = fmaf(w, uhi(he), ay);
                    }
                ull v = upack(selu_f(ax), selu_f(ay));
                H2[sidx(o, p)] = v;
                if (e == 1) H2[sidx(o, -1)]  = v;   // q=-1  <- p=1
                if (e == 2) H2[sidx(o, 512)] = v;   // q=512 <- p=510
            }
        }
        __syncthreads();

        // ---- L34: composed 4->1 k13 from H2 + SELU -> out ----
        const size_t ob0 = ((size_t)(2 * bp)     * 50 + sig) * NPOS;
        const size_t ob1 = ((size_t)(2 * bp + 1) * 50 + sig) * NPOS;
        {
            ull a4[4];
            ull b = Wsm[F2_BE34S];
            #pragma unroll
            for (int r = 0; r < 4; r++) a4[r] = b;
            #pragma unroll
            for (int c = 0; c < 4; c++) {
                ull h[16];
                #pragma unroll
                for (int t = 0; t < 16; t++) h[t] = H2[sidx(c, base - 6 + t)];
                const ull* wp = Wsm + F2_W34S + c * 13;
                #pragma unroll
                for (int t = 0; t < 13; t++) {
                    ull w = wp[t];
                    #pragma unroll
                    for (int r = 0; r < 4; r++)
                        a4[r] = ffma2u(w, h[t + r], a4[r]);
                }
            }
            if (!is_lo && !is_hi) {
                ull v0 = selu_u(a4[0]), v1 = selu_u(a4[1]);
                ull v2 = selu_u(a4[2]), v3 = selu_u(a4[3]);
                *reinterpret_cast<float4*>(out + ob0 + base) =
                    make_float4(ulo(v0), ulo(v1), ulo(v2), ulo(v3));
                *reinterpret_cast<float4*>(out + ob1 + base) =
                    make_float4(uhi(v0), uhi(v1), uhi(v2), uhi(v3));
            }
        }
        // distributed L34 edge outputs on warp 1: tids 32..39 -> p in {0..3,508..511}
        if (tid >= 32 && tid < 40) {
            int k = tid - 32;
            int p = (k < 4) ? k : 504 + k;
            float ax = Wf[OFF_B4R], ay = ax;
            #pragma unroll
            for (int m = 0; m < 2; m++)
                #pragma unroll
                for (int j = 0; j < 5; j++) {
                    int s = refl(p - 4 + 2 * j);
                    float hx = Wf[OFF_B3R + m], hy = hx;
                    #pragma unroll
                    for (int c = 0; c < 4; c++)
                        #pragma unroll
                        for (int kk = 0; kk < 5; kk++) {
                            float w = Wf[OFF_W3R + m * 20 + c * 5 + kk];
                            ull hv = H2[sidx(c, s - 2 + kk)];
                            hx = fmaf(w, ulo(hv), hx);
                            hy = fmaf(w, uhi(hv), hy);
                        }
                    float w4v = Wf[OFF_W4R + m * 5 + j];
                    ax = fmaf(w4v, hx, ax);
                    ay = fmaf(w4v, hy, ay);
                }
            out[ob0 + p] = selu_f(ax);
            out[ob1 + p] = selu_f(ay);
        }
    }
}

// ---------------------------------------------------------------------------
// launch
// ---------------------------------------------------------------------------

static const int SMEM_PREP = (16 * CST) * (int)sizeof(float2) + 336 * 4 + 64 * (int)sizeof(float2);
static const int SMEM_SIG  = (360 + 8 * CST + 64) * (int)sizeof(ull);

extern "C" void kernel_launch(void* const* d_in, const int* in_sizes, int n_in,
                              void* d_out, int out_size) {
    const float* lat  = (const float*)d_in[0];
    const float* shw1 = (const float*)d_in[1];
    const float* shb1 = (const float*)d_in[2];
    const float* shw2 = (const float*)d_in[3];
    const float* shb2 = (const float*)d_in[4];
    const float* lng  = (const float*)d_in[5];
    const float* lnb  = (const float*)d_in[6];
    const float* sgw1 = (const float*)d_in[7];
    const float* sgb1 = (const float*)d_in[8];
    const float* sgw2 = (const float*)d_in[9];
    const float* sgb2 = (const float*)d_in[10];
    const float* sgw3 = (const float*)d_in[11];
    const float* sgb3 = (const float*)d_in[12];
    const float* sgw4 = (const float*)d_in[13];
    const float* sgb4 = (const float*)d_in[14];
    float* out = (float*)d_out;

    cudaFuncSetAttribute(prep_kernel, cudaFuncAttributeMaxDynamicSharedMemorySize, SMEM_PREP);
    cudaFuncSetAttribute(sig_kernel,  cudaFuncAttributeMaxDynamicSharedMemorySize, SMEM_SIG);

    prep_kernel<<<NBP + NSIG, 512, SMEM_PREP>>>(lat, shw1, shb1, shw2, shb2, lng, lnb,
                                                sgw1, sgb1, sgw2, sgb2,
                                                sgw3, sgb3, sgw4, sgb4);
    sig_kernel<<<NCTA, 128, SMEM_SIG>>>(out);
}

// round 16
// speedup vs baseline: 1.3502x; 1.1061x over previous
#include <cuda_runtime.h>

// ---------------------------------------------------------------------------
// signalEncoding: B=256, S=512, SF=4, NSIG=50
// prep+wcomp merged (one launch). sig: 128 thr, 4 pos/thread, swizzled SMEM,
// ull f32x2, 6 CTAs/SM, 3 barriers/item. L12 composed (4->4 k11) + SELU;
// L34 composed (4->1 k13); no H3. Branchless SELU.
// R16: fix WCHUNKS (125 x 16B = full 498-float hot block; R15 copied half).
// ---------------------------------------------------------------------------

#define NPOS 512
#define HALO 8
#define CST  528
#define NBP  128
#define NSIG 50
#define NITEM (NBP * NSIG)   // 6400
#define NCTA  888            // 6 CTAs/SM * 148 SMs = one wave
#define WSTRIDE 948
#define WTOTAL  948
#define WCHUNKS 125          // 16B chunks of hot W block (498 floats = 1992B -> 125*16B)

typedef unsigned long long ull;

// ull-index offsets into weight block (splatted f32x2 sections, HOT = smem)
#define F2_W12S  0    // [o*48 + c*12 + t] t<11 real (192)
#define F2_BE12S 192  // [o] (4)
#define F2_W34S  196  // [c*13 + t] (52)
#define F2_BE34S 248  // (1)
// raw float offsets (GLOBAL only in sig)
#define OFF_W3R  498  // 40: [m*20 + c*5 + k]
#define OFF_B3R  538  // 2
#define OFF_W4R  540  // 10: [m*5 + j]
#define OFF_B4R  550  // 1
#define OFF_W2R  551  // 160
#define OFF_B2R  711  // 4
#define OFF_W1R  716  // 224
#define OFF_B1R  940  // 8

__device__ __forceinline__ int sidx(int c, int p) {
    int q = p + HALO;
    return c * CST + (q ^ ((q >> 4) & 3));
}

__device__ __forceinline__ int refl(int q) {
    q = q < 0 ? -q : q;
    return q > 511 ? 1022 - q : q;
}

// ---- ull-pure packed math ----
__device__ __forceinline__ ull ffma2u(ull a, ull b, ull c) {
    ull d;
    asm("fma.rn.f32x2 %0, %1, %2, %3;" : "=l"(d) : "l"(a), "l"(b), "l"(c));
    return d;
}
__device__ __forceinline__ float ulo(ull v) { return __uint_as_float((unsigned)v); }
__device__ __forceinline__ float uhi(ull v) { return __uint_as_float((unsigned)(v >> 32)); }
__device__ __forceinline__ ull upack(float x, float y) {
    return (ull)__float_as_uint(x) | ((ull)__float_as_uint(y) << 32);
}
// branchless SELU (exact selection; see R14)
__device__ __forceinline__ float selu_f(float x) {
    const float SC = 1.0507009873554805f;
    const float SA = 1.7580993408473766f;
    float p = SC * x;
    float e = SA * (__expf(x) - 1.0f);
    return fmaxf(p, 0.0f) + fminf(e, 0.0f);
}
__device__ __forceinline__ ull selu_u(ull v) {
    return upack(selu_f(ulo(v)), selu_f(uhi(v)));
}

// ---- float2 helpers for prep ----
union F2U { float2 f; unsigned long long u; };
__device__ __forceinline__ float2 ffma2(float2 a, float2 b, float2 c) {
    F2U ua, ub, uc, ud;
    ua.f = a; ub.f = b; uc.f = c;
    asm("fma.rn.f32x2 %0, %1, %2, %3;" : "=l"(ud.u) : "l"(ua.u), "l"(ub.u), "l"(uc.u));
    return ud.f;
}
__device__ __forceinline__ float2 splat(float w) { return make_float2(w, w); }
__device__ __forceinline__ float2 add2(float2 a, float2 b) {
    return make_float2(a.x + b.x, a.y + b.y);
}
__device__ __forceinline__ float selu_s(float x) {
    const float SC = 1.0507009873554805f;
    const float SA = 1.7580993408473766f;
    return x > 0.f ? SC * x : SA * expm1f(x);
}
__device__ __forceinline__ float2 selu2(float2 v) {
    return make_float2(selu_s(v.x), selu_s(v.y));
}
__device__ __forceinline__ void fill_halo_sw(float2* buf, int C, int tid) {
    if (tid < C * 8) {
        int c = tid >> 3, k = tid & 7;
        if (k < 4) { int i = k + 1; buf[sidx(c, -i)]      = buf[sidx(c, i)]; }
        else       { int i = k - 3; buf[sidx(c, 511 + i)] = buf[sidx(c, 511 - i)]; }
    }
}

__device__ float2 g_D[NBP * 4 * NPOS];
__device__ __align__(16) float g_W[NSIG * WSTRIDE];

// ---------------------------------------------------------------------------
// wcomp body (unchanged)
// ---------------------------------------------------------------------------

__device__ void wcomp_body(int sig, int t,
                           const float* sw1, const float* sb1,
                           const float* sw2, const float* sb2,
                           const float* sw3, const float* sb3,
                           const float* sw4, const float* sb4) {
    float* w = g_W + sig * WSTRIDE;
    for (int i = t; i < WTOTAL; i += 128) {
        float v;
        if (i < 384) {
            int k = i >> 1, o = k / 48, r = k % 48, c = r / 12, tt = r % 12;
            if (tt == 11) v = 0.f;
            else {
                float s = 0.f;
                const float* w2p = sw2 + sig * 160 + o * 40;
                const float* w1p = sw1 + sig * 224;
                #pragma unroll
                for (int m = 0; m < 8; m++)
                    #pragma unroll
                    for (int j2 = 0; j2 < 5; j2++) {
                        int j1 = tt - j2;
                        if (j1 >= 0 && j1 <= 6)
                            s += w2p[m * 5 + j2] * w1p[m * 28 + c * 7 + j1];
                    }
                v = s;
            }
        } else if (i < 392) {
            int o = (i - 384) >> 1;
            float s = sb2[sig * 4 + o];
            #pragma unroll
            for (int m = 0; m < 8; m++) {
                float sm_ = 0.f;
                #pragma unroll
                for (int j2 = 0; j2 < 5; j2++) sm_ += sw2[sig * 160 + o * 40 + m * 5 + j2];
                s += sm_ * sb1[sig * 8 + m];
            }
            v = s;
        } else if (i < 496) {
            int k = (i - 392) >> 1, c = k / 13, tt = k % 13;
            float s = 0.f;
            #pragma unroll
            for (int m = 0; m < 2; m++)
                #pragma unroll
                for (int j4 = 0; j4 < 5; j4++) {
                    int j3 = tt - 2 * j4;
                    if (j3 >= 0 && j3 <= 4)
                        s += sw4[sig * 10 + m * 5 + j4] * sw3[sig * 40 + m * 20 + c * 5 + j3];
                }
            v = s;
        } else if (i < 498) {
            float s = sb4[sig];
            #pragma unroll
            for (int m = 0; m < 2; m++) {
                float sm_ = 0.f;
                #pragma unroll
                for (int j4 = 0; j4 < 5; j4++) sm_ += sw4[sig * 10 + m * 5 + j4];
                s += sm_ * sb3[sig * 2 + m];
            }
            v = s;
        } else if (i < 538) {
            v = sw3[sig * 40 + (i - OFF_W3R)];
        } else if (i < 540) {
            v = sb3[sig * 2 + (i - OFF_B3R)];
        } else if (i < 550) {
            v = sw4[sig * 10 + (i - OFF_W4R)];
        } else if (i < 551) {
            v = sb4[sig];
        } else if (i < 711) {
            v = sw2[sig * 160 + (i - OFF_W2R)];
        } else if (i < 715) {
            v = sb2[sig * 4 + (i - OFF_B2R)];
        } else if (i < 716) {
            v = 0.f;  // pad
        } else if (i < 940) {
            v = sw1[sig * 224 + (i - OFF_W1R)];
        } else {
            v = sb1[sig * 8 + (i - OFF_B1R)];
        }
        w[i] = v;
    }
}

// ---------------------------------------------------------------------------
// merged prep (+wcomp tail blocks). grid = 128 + 50, block = 512. (unchanged)
// ---------------------------------------------------------------------------

__device__ __forceinline__ void shared_conv1(const float2* S, float2* Dst,
                                             const float* w1, const float* b1, int t) {
    #pragma unroll
    for (int o = 0; o < 8; o++) {
        float2 acc = splat(b1[o]);
        #pragma unroll
        for (int c = 0; c < 4; c++)
            #pragma unroll
            for (int j = 0; j < 5; j++) {
                float w = w1[o * 20 + c * 5 + j];
                acc = ffma2(splat(w), S[sidx(c, t - 2 + j)], acc);
            }
        Dst[sidx(o, t)] = selu2(acc);
    }
}

__device__ __forceinline__ void shared_conv2(const float2* S, const float* w2,
                                             const float* b2, int t, float2 out[4]) {
    #pragma unroll
    for (int o = 0; o < 4; o++) {
        float2 acc = splat(b2[o]);
        #pragma unroll
        for (int c = 0; c < 8; c++)
            #pragma unroll
            for (int j = 0; j < 5; j++) {
                float w = w2[o * 40 + c * 5 + j];
                acc = ffma2(splat(w), S[sidx(c, t - 4 + 2 * j)], acc);
            }
        out[o] = acc;
    }
}

extern "C" __global__ void __launch_bounds__(512)
prep_kernel(const float* __restrict__ lat,
            const float* __restrict__ sw1, const float* __restrict__ sb1,
            const float* __restrict__ sw2, const float* __restrict__ sb2,
            const float* __restrict__ lng, const float* __restrict__ lnb,
            const float* __restrict__ gw1, const float* __restrict__ gb1,
            const float* __restrict__ gw2, const float* __restrict__ gb2,
            const float* __restrict__ gw3, const float* __restrict__ gb3,
            const float* __restrict__ gw4, const float* __restrict__ gb4) {
    if (blockIdx.x >= NBP) {
        if (threadIdx.x < 128)
            wcomp_body(blockIdx.x - NBP, threadIdx.x,
                       gw1, gb1, gw2, gb2, gw3, gb3, gw4, gb4);
        return;
    }

    extern __shared__ unsigned char sm[];
    float2* X   = (float2*)sm;
    float2* A   = X + 4 * CST;
    float2* Bu  = A + 8 * CST;
    float*  W   = (float*)(Bu + 4 * CST);
    float2* RED = (float2*)(W + 336);

    const int t  = threadIdx.x;
    const int bp = blockIdx.x;
    const int lane = t & 31, wid = t >> 5;

    if (t < 332) {
        float v;
        if      (t < 160) v = sw1[t];
        else if (t < 168) v = sb1[t - 160];
        else if (t < 328) v = sw2[t - 168];
        else              v = sb2[t - 328];
        W[t] = v;
    }
    const float* w1 = W, * b1 = W + 160, * w2 = W + 168, * b2 = W + 328;

    float4 v0 = reinterpret_cast<const float4*>(lat + (size_t)(2 * bp)     * 2048)[t];
    float4 v1 = reinterpret_cast<const float4*>(lat + (size_t)(2 * bp + 1) * 2048)[t];
    X[sidx(0, t)] = make_float2(v0.x, v1.x);
    X[sidx(1, t)] = make_float2(v0.y, v1.y);
    X[sidx(2, t)] = make_float2(v0.z, v1.z);
    X[sidx(3, t)] = make_float2(v0.w, v1.w);
    __syncthreads();
    fill_halo_sw(X, 4, t);
    __syncthreads();

    shared_conv1(X, A, w1, b1, t);
    __syncthreads(); fill_halo_sw(A, 8, t); __syncthreads();
    {
        float2 tmp[4];
        shared_conv2(A, w2, b2, t, tmp);
        __syncthreads();
        #pragma unroll
        for (int c = 0; c < 4; c++) Bu[sidx(c, t)] = tmp[c];
    }
    __syncthreads(); fill_halo_sw(Bu, 4, t); __syncthreads();

    shared_conv1(Bu, A, w1, b1, t);
    __syncthreads(); fill_halo_sw(A, 8, t); __syncthreads();
    float2 dv[4];
    {
        float2 cc[4];
        shared_conv2(A, w2, b2, t, cc);
        #pragma unroll
        for (int c = 0; c < 4; c++) dv[c] = add2(cc[c], X[sidx(c, t)]);
    }

    float2 mean[4], var[4];
    {
        float2 sv[4];
        #pragma unroll
        for (int c = 0; c < 4; c++) sv[c] = dv[c];
        #pragma unroll
        for (int c = 0; c < 4; c++)
            for (int off = 16; off; off >>= 1) {
                sv[c].x += __shfl_xor_sync(0xffffffffu, sv[c].x, off);
                sv[c].y += __shfl_xor_sync(0xffffffffu, sv[c].y, off);
            }
        if (lane == 0)
            #pragma unroll
            for (int c = 0; c < 4; c++) RED[c * 16 + wid] = sv[c];
        __syncthreads();
        if (t < 32) {
            #pragma unroll
            for (int c = 0; c < 4; c++) {
                float2 v = (lane < 16) ? RED[c * 16 + lane] : make_float2(0.f, 0.f);
                for (int off = 8; off; off >>= 1) {
                    v.x += __shfl_xor_sync(0xffffffffu, v.x, off);
                    v.y += __shfl_xor_sync(0xffffffffu, v.y, off);
                }
                if (lane == 0) RED[c * 16] = v;
            }
        }
        __syncthreads();
        const float inv = 1.0f / 512.0f;
        #pragma unroll
        for (int c = 0; c < 4; c++) {
            float2 s = RED[c * 16];
            mean[c] = make_float2(s.x * inv, s.y * inv);
        }
        __syncthreads();
    }
    {
        float2 sv[4];
        #pragma unroll
        for (int c = 0; c < 4; c++) {
            float dx = dv[c].x - mean[c].x, dy = dv[c].y - mean[c].y;
            sv[c] = make_float2(dx * dx, dy * dy);
        }
        #pragma unroll
        for (int c = 0; c < 4; c++)
            for (int off = 16; off; off >>= 1) {
                sv[c].x += __shfl_xor_sync(0xffffffffu, sv[c].x, off);
                sv[c].y += __shfl_xor_sync(0xffffffffu, sv[c].y, off);
            }
        if (lane == 0)
            #pragma unroll
            for (int c = 0; c < 4; c++) RED[c * 16 + wid] = sv[c];
        __syncthreads();
        if (t < 32) {
            #pragma unroll
            for (int c = 0; c < 4; c++) {
                float2 v = (lane < 16) ? RED[c * 16 + lane] : make_float2(0.f, 0.f);
                for (int off = 8; off; off >>= 1) {
                    v.x += __shfl_xor_sync(0xffffffffu, v.x, off);
                    v.y += __shfl_xor_sync(0xffffffffu, v.y, off);
                }
                if (lane == 0) RED[c * 16] = v;
            }
        }
        __syncthreads();
        const float inv = 1.0f / 512.0f;
        #pragma unroll
        for (int c = 0; c < 4; c++) {
            float2 s = RED[c * 16];
            var[c] = make_float2(s.x * inv, s.y * inv);
        }
    }

    const float EPS = 1e-10f;
    float g = lng[t], bb = lnb[t];
    #pragma unroll
    for (int c = 0; c < 4; c++) {
        float rx = 1.0f / sqrtf(var[c].x + EPS);
        float ry = 1.0f / sqrtf(var[c].y + EPS);
        float2 dn;
        dn.x = (dv[c].x - mean[c].x) * rx * g + bb;
        dn.y = (dv[c].y - mean[c].y) * ry * g + bb;
        g_D[(size_t)(bp * 4 + c) * NPOS + t] = dn;
    }
}

// ---------------------------------------------------------------------------
// sig: 128 threads, 4 pos/thread, 6 CTAs/SM.
// ---------------------------------------------------------------------------

extern "C" __global__ void __launch_bounds__(128, 6)
sig_kernel(float* __restrict__ out) {
    extern __shared__ ull smu[];
    ull* Wsm = smu;                 // 256 ull (hot: 250 used, padded)
    ull* D   = smu + 256;           // 4*CST
    ull* H2  = D + 4 * CST;         // 4*CST
    ull* He  = H2 + 4 * CST;        // 64 (stage: H1 edges; L34 phase: H3 edges)

    const int tid  = threadIdx.x;
    const int base = tid * 4;
    const bool is_lo = (tid == 0), is_hi = (tid == 127);

    const int kcta  = blockIdx.x;
    const int start = (int)(((long long)kcta * NITEM) / NCTA);
    const int end   = (int)(((long long)(kcta + 1) * NITEM) / NCTA);

    int cur_bp = -1;

    for (int it = start; it < end; ++it) {
        const int bp  = it / NSIG;
        const int sig = it - bp * NSIG;

        __syncthreads();   // prior item's smem reads complete

        if (bp != cur_bp) {
            const ull* gd = (const ull*)(g_D + (size_t)bp * 4 * NPOS);
            for (int i = tid; i < 4 * NPOS; i += 128) {
                int c = i >> 9, pp = i & 511;
                ull v = gd[i];
                D[sidx(c, pp)] = v;
                if (pp >= 1 && pp <= 5)     D[sidx(c, -pp)]       = v;
                if (pp >= 506 && pp <= 510) D[sidx(c, 1022 - pp)] = v;
            }
            cur_bp = bp;
            __syncthreads();
        }

        const float* gw = g_W + sig * WSTRIDE;

        // stage: tids >=64 async-copy hot W block (125 x 16B); tids <64 H1 edges
        if (tid >= 64) {
            for (int i = tid - 64; i < WCHUNKS; i += 64) {
                unsigned dst = (unsigned)__cvta_generic_to_shared(Wsm) + i * 16;
                const char* src = (const char*)gw + i * 16;
                asm volatile("cp.async.ca.shared.global [%0], [%1], 16;"
                             :: "r"(dst), "l"(src));
            }
            asm volatile("cp.async.commit_group;");
            asm volatile("cp.async.wait_group 0;");
        } else {
            int m = tid >> 3, kk = tid & 7;
            int q = kk < 4 ? kk : 508 + (kk - 4);
            float ax = gw[OFF_B1R + m], ay = ax;
            const float* w1p = gw + OFF_W1R + m * 28;
            #pragma unroll
            for (int c = 0; c < 4; c++)
                #pragma unroll
                for (int j1 = 0; j1 < 7; j1++) {
                    float w = w1p[c * 7 + j1];
                    ull dv = D[sidx(c, q - 3 + j1)];
                    ax = fmaf(w, ulo(dv), ax);
                    ay = fmaf(w, uhi(dv), ay);
                }
            He[tid] = upack(ax, ay);
        }
        __syncthreads();

        // ---- L12: composed 4->4 k11 (uniform); edge cells distributed ----
        {
            ull acc[4][4];
            #pragma unroll
            for (int o = 0; o < 4; o++) {
                ull b = Wsm[F2_BE12S + o];
                #pragma unroll
                for (int r = 0; r < 4; r++) acc[o][r] = b;
            }
            #pragma unroll
            for (int c = 0; c < 4; c++) {
                ull din[14];
                #pragma unroll
                for (int t = 0; t < 14; t++) din[t] = D[sidx(c, base - 5 + t)];
                #pragma unroll
                for (int o = 0; o < 4; o++) {
                    const ulonglong2* wp2 =
                        (const ulonglong2*)(Wsm + F2_W12S + o * 48 + c * 12);
                    #pragma unroll
                    for (int tt = 0; tt < 5; tt++) {
                        ulonglong2 wq = wp2[tt];
                        #pragma unroll
                        for (int r = 0; r < 4; r++)
                            acc[o][r] = ffma2u(wq.x, din[2 * tt + r], acc[o][r]);
                        #pragma unroll
                        for (int r = 0; r < 4; r++)
                            acc[o][r] = ffma2u(wq.y, din[2 * tt + 1 + r], acc[o][r]);
                    }
                    ull w10 = Wsm[F2_W12S + o * 48 + c * 12 + 10];
                    #pragma unroll
                    for (int r = 0; r < 4; r++)
                        acc[o][r] = ffma2u(w10, din[10 + r], acc[o][r]);
                }
            }
            // store composed values; skip edge cells (p in {0,1,510,511});
            // owner-exact halo mirrors for q in [-6,-2] and [513,517]
            #pragma unroll
            for (int o = 0; o < 4; o++)
                #pragma unroll
                for (int r = 0; r < 4; r++) {
                    if ((is_lo && r < 2) || (is_hi && r >= 2)) continue;
                    ull v = selu_u(acc[o][r]);
                    H2[sidx(o, base + r)] = v;
                    if (is_lo) {
                        if (r == 2) H2[sidx(o, -2)] = v;
                        if (r == 3) H2[sidx(o, -3)] = v;
                    } else if (tid == 1) {
                        if (r == 0) H2[sidx(o, -4)] = v;
                        if (r == 1) H2[sidx(o, -5)] = v;
                        if (r == 2) H2[sidx(o, -6)] = v;
                    } else if (tid == 126) {
                        if (r == 1) H2[sidx(o, 517)] = v;
                        if (r == 2) H2[sidx(o, 516)] = v;
                        if (r == 3) H2[sidx(o, 515)] = v;
                    } else if (is_hi) {
                        if (r == 0) H2[sidx(o, 514)] = v;
                        if (r == 1) H2[sidx(o, 513)] = v;
                    }
                }
            // distributed L12 edge tasks (raw w2 from GLOBAL): tids 0..15
            if (tid < 16) {
                int e = tid >> 2, o = tid & 3;
                int p = (e < 2) ? e : 508 + e;
                float ax = gw[OFF_B2R + o], ay = ax;
                #pragma unroll
                for (int m = 0; m < 8; m++)
                    #pragma unroll
                    for (int j2 = 0; j2 < 5; j2++) {
                        int q = refl(p - 2 + j2);
                        int k = q < 8 ? q : q - 504;
                        float w = gw[OFF_W2R + o * 40 + m * 5 + j2];
                        ull he = He[m * 8 + k];
                        ax = fmaf(w, ulo(he), ax);
                        ay = fmaf(w, uhi(he), ay);
                    }
                ull v = upack(selu_f(ax), selu_f(ay));
                H2[sidx(o, p)] = v;
                if (e == 1) H2[sidx(o, -1)]  = v;   // q=-1  <- p=1
                if (e == 2) H2[sidx(o, 512)] = v;   // q=512 <- p=510
            }
        }
        __syncthreads();

        // ---- L34: composed 4->1 k13 from H2 + SELU -> out ----
        const size_t ob0 = ((size_t)(2 * bp)     * 50 + sig) * NPOS;
        const size_t ob1 = ((size_t)(2 * bp + 1) * 50 + sig) * NPOS;
        {
            ull a4[4];
            ull b = Wsm[F2_BE34S];
            #pragma unroll
            for (int r = 0; r < 4; r++) a4[r] = b;
            #pragma unroll
            for (int c = 0; c < 4; c++) {
                ull h[16];
                #pragma unroll
                for (int t = 0; t < 16; t++) h[t] = H2[sidx(c, base - 6 + t)];
                const ull* wp = Wsm + F2_W34S + c * 13;
                #pragma unroll
                for (int t = 0; t < 13; t++) {
                    ull w = wp[t];
                    #pragma unroll
                    for (int r = 0; r < 4; r++)
                        a4[r] = ffma2u(w, h[t + r], a4[r]);
                }
            }
            if (!is_lo && !is_hi) {
                ull v0 = selu_u(a4[0]), v1 = selu_u(a4[1]);
                ull v2 = selu_u(a4[2]), v3 = selu_u(a4[3]);
                *reinterpret_cast<float4*>(out + ob0 + base) =
                    make_float4(ulo(v0), ulo(v1), ulo(v2), ulo(v3));
                *reinterpret_cast<float4*>(out + ob1 + base) =
                    make_float4(uhi(v0), uhi(v1), uhi(v2), uhi(v3));
            }
        }
        // L34 edge outputs, two-stage on warp 1 (tids 32..63):
        // stage 1: 32 lanes compute true H3[m][q] for q in {0..7, 504..511}
        // stage 2: 8 lanes combine via raw w4 (global) -> out
        if (tid >= 32 && tid < 64) {
            int l = tid - 32, m = l >> 4, t = l & 15;
            int q = (t < 8) ? t : 496 + t;           // 0..7 or 504..511
            float hx = gw[OFF_B3R + m], hy = hx;
            #pragma unroll
            for (int c = 0; c < 4; c++)
                #pragma unroll
                for (int k = 0; k < 5; k++) {
                    float w = gw[OFF_W3R + m * 20 + c * 5 + k];
                    ull hv = H2[sidx(c, q - 2 + k)];
                    hx = fmaf(w, ulo(hv), hx);
                    hy = fmaf(w, uhi(hv), hy);
                }
            He[l] = upack(hx, hy);                   // He reused as H3-edge store
            __syncwarp();
            if (l < 8) {
                int p = (l < 4) ? l : 504 + l;       // 0..3 or 508..511
                float ax = gw[OFF_B4R], ay = ax;
                #pragma unroll
                for (int m2 = 0; m2 < 2; m2++)
                    #pragma unroll
                    for (int j = 0; j < 5; j++) {
                        int s = refl(p - 4 + 2 * j);
                        int ti = (s < 8) ? s : s - 496;
                        float w = gw[OFF_W4R + m2 * 5 + j];
                        ull hv = He[m2 * 16 + ti];
                        ax = fmaf(w, ulo(hv), ax);
                        ay = fmaf(w, uhi(hv), ay);
                    }
                out[ob0 + p] = selu_f(ax);
                out[ob1 + p] = selu_f(ay);
            }
        }
    }
}

// ---------------------------------------------------------------------------
// launch
// ---------------------------------------------------------------------------

static const int SMEM_PREP = (16 * CST) * (int)sizeof(float2) + 336 * 4 + 64 * (int)sizeof(float2);
static const int SMEM_SIG  = (256 + 8 * CST + 64) * (int)sizeof(ull);

extern "C" void kernel_launch(void* const* d_in, const int* in_sizes, int n_in,
                              void* d_out, int out_size) {
    const float* lat  = (const float*)d_in[0];
    const float* shw1 = (const float*)d_in[1];
    const float* shb1 = (const float*)d_in[2];
    const float* shw2 = (const float*)d_in[3];
    const float* shb2 = (const float*)d_in[4];
    const float* lng  = (const float*)d_in[5];
    const float* lnb  = (const float*)d_in[6];
    const float* sgw1 = (const float*)d_in[7];
    const float* sgb1 = (const float*)d_in[8];
    const float* sgw2 = (const float*)d_in[9];
    const float* sgb2 = (const float*)d_in[10];
    const float* sgw3 = (const float*)d_in[11];
    const float* sgb3 = (const float*)d_in[12];
    const float* sgw4 = (const float*)d_in[13];
    const float* sgb4 = (const float*)d_in[14];
    float* out = (float*)d_out;

    cudaFuncSetAttribute(prep_kernel, cudaFuncAttributeMaxDynamicSharedMemorySize, SMEM_PREP);
    cudaFuncSetAttribute(sig_kernel,  cudaFuncAttributeMaxDynamicSharedMemorySize, SMEM_SIG);

    prep_kernel<<<NBP + NSIG, 512, SMEM_PREP>>>(lat, shw1, shb1, shw2, shb2, lng, lnb,
                                                sgw1, sgb1, sgw2, sgb2,
                                                sgw3, sgb3, sgw4, sgb4);
    sig_kernel<<<NCTA, 128, SMEM_SIG>>>(out);
}